// round 16
// baseline (speedup 1.0000x reference)
#include <cuda_runtime.h>
#include <cstdint>

#define NN 2048
#define FF 64
#define KT 64
#define NT (NN / KT)
#define RPB 64
#define THREADS 512
#define ST 68

typedef unsigned long long u64;

// Precomputed -0.5 * sum_f v[n,f]^2
__device__ float g_s[NN];

__global__ void fm_prep(const float* __restrict__ v) {
    int n = blockIdx.x * blockDim.x + threadIdx.x;
    if (n >= NN) return;
    const float4* vr = (const float4*)(v + (size_t)n * FF);
    float s = 0.f;
#pragma unroll
    for (int i = 0; i < FF / 4; i++) {
        float4 t = vr[i];
        s += t.x * t.x + t.y * t.y + t.z * t.z + t.w * t.w;
    }
    g_s[n] = -0.5f * s;
}

__device__ __forceinline__ void ffma2(u64& d, u64 a, u64 b) {
    asm("fma.rn.f32x2 %0, %1, %2, %0;" : "+l"(d) : "l"(a), "l"(b));
}
__device__ __forceinline__ u64 addx2(u64 a, u64 b) {
    u64 d;
    asm("add.rn.f32x2 %0, %1, %2;" : "=l"(d) : "l"(a), "l"(b));
    return d;
}
__device__ __forceinline__ u64 bcast(float f) {
    u64 d; unsigned u = __float_as_uint(f);
    asm("mov.b64 %0, {%1, %1};" : "=l"(d) : "r"(u));
    return d;
}
__device__ __forceinline__ float2 unpk(u64 a) {
    float lo, hi;
    asm("mov.b64 {%0, %1}, %2;" : "=f"(lo), "=f"(hi) : "l"(a));
    return make_float2(lo, hi);
}
__device__ __forceinline__ u64 shflx64(u64 v, int d) {
    unsigned lo = (unsigned)v, hi = (unsigned)(v >> 32);
    lo = __shfl_xor_sync(0xffffffffu, lo, d);
    hi = __shfl_xor_sync(0xffffffffu, hi, d);
    return (u64)lo | ((u64)hi << 32);
}

__global__ void __launch_bounds__(THREADS, 1)
fm_main(const float* __restrict__ x, const float* __restrict__ w0p,
        const float* __restrict__ w1, const float* __restrict__ v,
        float* __restrict__ out) {
    __shared__ __align__(16) float x_sh[KT * ST];   // [k][row], stride 68
    __shared__ __align__(16) float v_sh[KT * ST];   // [k][f],   stride 68
    __shared__ float w_sh[KT], s_sh[KT];

    const int tid = threadIdx.x;
    const int q   = tid & 7;            // k-interleave: k = kl*8 + q
    const int fg  = (tid >> 3) & 7;     // f-group: f = 8*fg .. 8*fg+7 (bit5 = warp bit)
    const int rg  = tid >> 6;           // row-group: rows 8*rg .. 8*rg+7
    const int pr  = tid & 63;           // stage row
    const int pc  = tid >> 6;           // stage col-group (0..7)
    const int row0 = blockIdx.x * RPB;

    u64 acc[32];                        // [r][p]: 8 rows x 4 f-pairs (8 f)
#pragma unroll
    for (int i = 0; i < 32; i++) acc[i] = 0ull;
    float scr[8];
#pragma unroll
    for (int r = 0; r < 8; r++) scr[r] = 0.f;

    float4 pfx[2], pfv[2];
    float pfws = 0.f;

    // ---- prefetch tile 0 ----
#pragma unroll
    for (int j = 0; j < 2; j++)
        pfx[j] = *(const float4*)(x + (size_t)(row0 + pr) * NN + 8 * pc + 4 * j);
#pragma unroll
    for (int it = 0; it < 2; it++) {
        int idx = it * THREADS + tid;   // float4 id 0..1023
        int k = idx >> 4, c = idx & 15;
        pfv[it] = *(const float4*)(v + (size_t)k * FF + 4 * c);
    }
    if (tid < KT) pfws = w1[tid];
    else if (tid < 2 * KT) pfws = g_s[tid - KT];

    for (int tile = 0; tile < NT; tile++) {
        // ---- store prefetched tile to smem ----
#pragma unroll
        for (int it = 0; it < 2; it++) {
            int idx = it * THREADS + tid;
            int k = idx >> 4, c = idx & 15;
            *(float4*)&v_sh[k * ST + 4 * c] = pfv[it];
        }
#pragma unroll
        for (int j = 0; j < 2; j++) {
            float4 t = pfx[j];
            int c0 = 8 * pc + 4 * j;
            x_sh[(c0 + 0) * ST + pr] = t.x;
            x_sh[(c0 + 1) * ST + pr] = t.y;
            x_sh[(c0 + 2) * ST + pr] = t.z;
            x_sh[(c0 + 3) * ST + pr] = t.w;
        }
        if (tid < KT) w_sh[tid] = pfws;
        else if (tid < 2 * KT) s_sh[tid - KT] = pfws;
        __syncthreads();

        // ---- prefetch next tile (overlaps compute) ----
        if (tile + 1 < NT) {
            const int t0 = (tile + 1) * KT;
#pragma unroll
            for (int j = 0; j < 2; j++)
                pfx[j] = *(const float4*)(x + (size_t)(row0 + pr) * NN + t0 + 8 * pc + 4 * j);
#pragma unroll
            for (int it = 0; it < 2; it++) {
                int idx = it * THREADS + tid;
                int k = idx >> 4, c = idx & 15;
                pfv[it] = *(const float4*)(v + (size_t)(t0 + k) * FF + 4 * c);
            }
            if (tid < KT) pfws = w1[t0 + tid];
            else if (tid < 2 * KT) pfws = g_s[t0 + tid - KT];
        }

        // ---- main compute: 8 rows x 8 f per thread, k = kl*8 + q ----
#pragma unroll
        for (int kl = 0; kl < 8; kl++) {
            const int kw = kl * 8 + q;
            const float* xr = x_sh + kw * ST + 8 * rg;
            float4 xa = *(const float4*)(xr);
            float4 xb = *(const float4*)(xr + 4);
            const float* vb = v_sh + kw * ST + 8 * fg;
            ulonglong2 va = *(const ulonglong2*)(vb);
            ulonglong2 vc = *(const ulonglong2*)(vb + 4);
            u64 vv[4] = {va.x, va.y, vc.x, vc.y};
            float xs[8] = {xa.x, xa.y, xa.z, xa.w, xb.x, xb.y, xb.z, xb.w};
#pragma unroll
            for (int r = 0; r < 8; r++) {
                u64 xx = bcast(xs[r]);
#pragma unroll
                for (int p = 0; p < 4; p++) ffma2(acc[r * 4 + p], vv[p], xx);
            }
        }

        // ---- linear/self term: this (q,fg) owns k = fg*8 + q ----
        {
            const int kw = fg * 8 + q;
            const float wv = w_sh[kw], sv = s_sh[kw];
            const float* xr = x_sh + kw * ST + 8 * rg;
#pragma unroll
            for (int r = 0; r < 8; r++) {
                float xv = xr[r];
                scr[r] = fmaf(xv, fmaf(xv, sv, wv), scr[r]);
            }
        }
        __syncthreads();
    }

    // ---- epilogue ----
    // 1) sum xv partials over the 8 q-lanes (lane bits 0..2)
#pragma unroll
    for (int d = 1; d <= 4; d <<= 1)
#pragma unroll
        for (int i = 0; i < 32; i++) acc[i] = addx2(acc[i], shflx64(acc[i], d));

    // 2) per-row square-sum over this thread's 8 f, then in-warp reductions
    float pwv[8], scv[8];
#pragma unroll
    for (int r = 0; r < 8; r++) {
        u64 sq = 0ull;
#pragma unroll
        for (int p = 0; p < 4; p++) ffma2(sq, acc[r * 4 + p], acc[r * 4 + p]);
        float2 s2 = unpk(sq);
        float pw = s2.x + s2.y;
        // reduce pw over fg-low lanes (bits 3..4); q-lanes already identical
        pw += __shfl_xor_sync(0xffffffffu, pw, 8);
        pw += __shfl_xor_sync(0xffffffffu, pw, 16);
        pwv[r] = pw;
        // scr owned disjointly by (q, fg-low) within warp: reduce bits 0..4
        float sc = scr[r];
        sc += __shfl_xor_sync(0xffffffffu, sc, 1);
        sc += __shfl_xor_sync(0xffffffffu, sc, 2);
        sc += __shfl_xor_sync(0xffffffffu, sc, 4);
        sc += __shfl_xor_sync(0xffffffffu, sc, 8);
        sc += __shfl_xor_sync(0xffffffffu, sc, 16);
        scv[r] = sc;
    }

    // 3) cross-warp combine over fg bit 2 (tid bit 5) via shared
    float* bufp = x_sh;          // [rg][half][r] : 8*2*8 = 128 floats
    float* bufs = x_sh + 256;
    const int lane = tid & 31;
    const int half = (tid >> 5) & 1;
    if (lane < 8) {
        bufp[rg * 16 + half * 8 + lane] = pwv[lane];
        bufs[rg * 16 + half * 8 + lane] = scv[lane];
    }
    __syncthreads();
    if (tid < RPB) {
        int rgg = tid >> 3, rr = tid & 7;
        float pw = bufp[rgg * 16 + rr] + bufp[rgg * 16 + 8 + rr];
        float sc = bufs[rgg * 16 + rr] + bufs[rgg * 16 + 8 + rr];
        out[row0 + tid] = w0p[0] + sc + 0.5f * pw;
    }
}

extern "C" void kernel_launch(void* const* d_in, const int* in_sizes, int n_in,
                              void* d_out, int out_size) {
    const float* x  = (const float*)d_in[0];
    const float* w0 = (const float*)d_in[1];
    const float* w1 = (const float*)d_in[2];
    const float* v  = (const float*)d_in[3];
    float* out = (float*)d_out;
    int B = in_sizes[0] / NN;

    fm_prep<<<(NN + 255) / 256, 256>>>(v);
    fm_main<<<B / RPB, THREADS>>>(x, w0, w1, v, out);
}